// round 1
// baseline (speedup 1.0000x reference)
#include <cuda_runtime.h>
#include <math.h>

#define BSZ 4
#define SEQ 2048
#define EMB 1024
#define NH 16
#define HD 64
#define FFD 4096
#define MTOK 8192   // BSZ*SEQ

// ---------------- scratch (static device allocations, allowed) -------------
__device__ float g_h [MTOK * EMB];   // LN1 out, later attention output y
__device__ float g_q [MTOK * EMB];   // Q, later LN2 out
__device__ float g_k [MTOK * EMB];
__device__ float g_v [MTOK * EMB];
__device__ float g_ff[MTOK * FFD];   // GELU(h2@W1+b1)

// ---------------------------- LayerNorm ------------------------------------
__global__ __launch_bounds__(256) void ln_kernel(
    const float* __restrict__ x, const float* __restrict__ g,
    const float* __restrict__ bta, float* __restrict__ out)
{
    int row = blockIdx.x;
    int t = threadIdx.x;                        // 256 threads, 4 floats each
    const float4* xr = (const float4*)(x + (size_t)row * EMB);
    float4 v = xr[t];
    float s  = v.x + v.y + v.z + v.w;
    float ss = v.x*v.x + v.y*v.y + v.z*v.z + v.w*v.w;
    #pragma unroll
    for (int o = 16; o; o >>= 1) {
        s  += __shfl_xor_sync(0xFFFFFFFFu, s,  o);
        ss += __shfl_xor_sync(0xFFFFFFFFu, ss, o);
    }
    __shared__ float sh_s[8], sh_ss[8];
    __shared__ float s_mu, s_rstd;
    int w = t >> 5;
    if ((t & 31) == 0) { sh_s[w] = s; sh_ss[w] = ss; }
    __syncthreads();
    if (t == 0) {
        float S = 0.f, SS = 0.f;
        #pragma unroll
        for (int i = 0; i < 8; i++) { S += sh_s[i]; SS += sh_ss[i]; }
        float mu  = S * (1.0f / EMB);
        float var = SS * (1.0f / EMB) - mu * mu;
        s_mu = mu; s_rstd = rsqrtf(var + 1e-5f);
    }
    __syncthreads();
    float mu = s_mu, rs = s_rstd;
    float4 gv = ((const float4*)g)[t];
    float4 bv = ((const float4*)bta)[t];
    float4 o;
    o.x = (v.x - mu) * rs * gv.x + bv.x;
    o.y = (v.y - mu) * rs * gv.y + bv.y;
    o.z = (v.z - mu) * rs * gv.z + bv.z;
    o.w = (v.w - mu) * rs * gv.w + bv.w;
    ((float4*)(out + (size_t)row * EMB))[t] = o;
}

// ------------------------------- GEMM ---------------------------------------
// C[M,N] = A[M,K] @ B[K,N] + bias  (+gelu | +residual)
// 128x128 tile, BK=8, 256 threads, 8x8 per-thread register tile.
// mode: 0 = bias only, 1 = bias+exact GELU, 2 = bias+residual add
__global__ __launch_bounds__(256) void gemm_kernel(
    const float* __restrict__ A, const float* __restrict__ B,
    const float* __restrict__ bias, const float* __restrict__ resid,
    float* __restrict__ C, int M, int N, int K, int mode)
{
    __shared__ float As[8][128];
    __shared__ float Bs[8][128];
    int tid = threadIdx.x;
    int tx = tid & 15, ty = tid >> 4;
    int bm = blockIdx.y * 128, bn = blockIdx.x * 128;

    float acc[8][8];
    #pragma unroll
    for (int i = 0; i < 8; i++)
        #pragma unroll
        for (int j = 0; j < 8; j++) acc[i][j] = 0.f;

    int ar = tid >> 1, ak = (tid & 1) * 4;          // A: 128 rows x 8 k
    int br = tid >> 5, bc = (tid & 31) * 4;         // B: 8 k x 128 cols
    const float* Aptr = A + (size_t)(bm + ar) * K + ak;
    const float* Bptr = B + (size_t)br * N + bn + bc;

    for (int k0 = 0; k0 < K; k0 += 8) {
        float4 av = *(const float4*)(Aptr + k0);
        float4 bv = *(const float4*)(Bptr + (size_t)k0 * N);
        __syncthreads();
        As[ak + 0][ar] = av.x; As[ak + 1][ar] = av.y;
        As[ak + 2][ar] = av.z; As[ak + 3][ar] = av.w;
        *(float4*)&Bs[br][bc] = bv;
        __syncthreads();
        #pragma unroll
        for (int kk = 0; kk < 8; kk++) {
            float a[8], b[8];
            #pragma unroll
            for (int i = 0; i < 8; i++) a[i] = As[kk][i * 16 + ty];
            #pragma unroll
            for (int j = 0; j < 8; j++) b[j] = Bs[kk][j * 16 + tx];
            #pragma unroll
            for (int i = 0; i < 8; i++)
                #pragma unroll
                for (int j = 0; j < 8; j++) acc[i][j] += a[i] * b[j];
        }
    }

    #pragma unroll
    for (int i = 0; i < 8; i++) {
        int row = bm + i * 16 + ty;
        #pragma unroll
        for (int j = 0; j < 8; j++) {
            int col = bn + j * 16 + tx;
            float v = acc[i][j] + bias[col];
            if (mode == 1) {
                v = 0.5f * v * (1.0f + erff(v * 0.70710678118654752f));
            } else if (mode == 2) {
                v += resid[(size_t)row * N + col];
            }
            C[(size_t)row * N + col] = v;
        }
    }
}

// --------------------------- Flash attention --------------------------------
// One block per (bh, 32-row q tile). 128 threads. Causal, online softmax.
#define TQ 32
#define TK 32
#define PD 65    // padded smem row (conflict-free column reads)

__global__ __launch_bounds__(128) void attn_kernel(
    const float* __restrict__ Q, const float* __restrict__ Kg,
    const float* __restrict__ V, float* __restrict__ Y)
{
    int qt = blockIdx.x;                 // q tile (0..63)
    int bh = blockIdx.y;                 // b*NH + h
    int b = bh >> 4, h = bh & 15;
    int tid = threadIdx.x;

    __shared__ float Qs[TQ][PD], Ks[TK][PD], Vs[TK][PD];
    __shared__ float Ss[TQ][TK + 1];
    __shared__ float m_s[TQ], l_s[TQ], corr_s[TQ];

    // load Q tile, pre-scaled by 1/sqrt(HD)
    for (int idx = tid; idx < TQ * HD; idx += 128) {
        int r = idx >> 6, d = idx & 63;
        Qs[r][d] = Q[((size_t)(b * SEQ + qt * TQ + r)) * EMB + h * HD + d] * 0.125f;
    }
    if (tid < TQ) { m_s[tid] = -INFINITY; l_s[tid] = 0.f; }

    int r  = tid >> 2;      // owned q row (0..31)
    int cg = tid & 3;       // col/dim group (0..3)
    float o[16];
    #pragma unroll
    for (int i = 0; i < 16; i++) o[i] = 0.f;

    for (int kt = 0; kt <= qt; kt++) {
        __syncthreads();
        for (int idx = tid; idx < TK * HD; idx += 128) {
            int rr = idx >> 6, d = idx & 63;
            size_t g = ((size_t)(b * SEQ + kt * TK + rr)) * EMB + h * HD + d;
            Ks[rr][d] = Kg[g];
            Vs[rr][d] = V[g];
        }
        __syncthreads();

        // scores: 8 cols per thread
        float sc[8];
        #pragma unroll
        for (int j = 0; j < 8; j++) sc[j] = 0.f;
        #pragma unroll 4
        for (int d = 0; d < HD; d++) {
            float qv = Qs[r][d];
            #pragma unroll
            for (int j = 0; j < 8; j++) sc[j] += qv * Ks[cg * 8 + j][d];
        }
        int grow = qt * TQ + r;
        #pragma unroll
        for (int j = 0; j < 8; j++) {
            int gc = kt * TK + cg * 8 + j;
            Ss[r][cg * 8 + j] = (gc <= grow) ? sc[j] : -1e30f;
        }
        __syncthreads();

        // online softmax, one thread per row
        if (tid < TQ) {
            float rmax = -INFINITY;
            #pragma unroll 8
            for (int c = 0; c < TK; c++) rmax = fmaxf(rmax, Ss[tid][c]);
            float mn = fmaxf(m_s[tid], rmax);
            float corr = expf(m_s[tid] - mn);
            float sum = 0.f;
            #pragma unroll 8
            for (int c = 0; c < TK; c++) {
                float p = expf(Ss[tid][c] - mn);
                Ss[tid][c] = p;
                sum += p;
            }
            l_s[tid] = l_s[tid] * corr + sum;
            m_s[tid] = mn;
            corr_s[tid] = corr;
        }
        __syncthreads();

        // O update: 16 dims per thread, accumulators in registers
        float corr = corr_s[r];
        #pragma unroll
        for (int i = 0; i < 16; i++) o[i] *= corr;
        #pragma unroll 4
        for (int c = 0; c < TK; c++) {
            float p = Ss[r][c];
            #pragma unroll
            for (int i = 0; i < 16; i++) o[i] += p * Vs[c][cg * 16 + i];
        }
    }

    float inv = 1.0f / l_s[r];
    size_t base = ((size_t)(b * SEQ + qt * TQ + r)) * EMB + h * HD + cg * 16;
    #pragma unroll
    for (int i = 0; i < 16; i++) Y[base + i] = o[i] * inv;
}

// ------------------------------- launch -------------------------------------
extern "C" void kernel_launch(void* const* d_in, const int* in_sizes, int n_in,
                              void* d_out, int out_size)
{
    const float* x     = (const float*)d_in[0];
    const float* Wq    = (const float*)d_in[1];
    const float* bq    = (const float*)d_in[2];
    const float* Wk    = (const float*)d_in[3];
    const float* bk    = (const float*)d_in[4];
    const float* Wv    = (const float*)d_in[5];
    const float* bv    = (const float*)d_in[6];
    const float* Wo    = (const float*)d_in[7];
    const float* bo    = (const float*)d_in[8];
    const float* g1    = (const float*)d_in[9];
    const float* beta1 = (const float*)d_in[10];
    const float* g2    = (const float*)d_in[11];
    const float* beta2 = (const float*)d_in[12];
    const float* W1    = (const float*)d_in[13];
    const float* b1    = (const float*)d_in[14];
    const float* W2    = (const float*)d_in[15];
    const float* b2    = (const float*)d_in[16];
    float* out = (float*)d_out;

    float *h, *q, *k, *v, *ff;
    cudaGetSymbolAddress((void**)&h,  g_h);
    cudaGetSymbolAddress((void**)&q,  g_q);
    cudaGetSymbolAddress((void**)&k,  g_k);
    cudaGetSymbolAddress((void**)&v,  g_v);
    cudaGetSymbolAddress((void**)&ff, g_ff);

    dim3 blk(256);
    dim3 gE(EMB / 128, MTOK / 128);   // N=1024 GEMMs
    dim3 gF(FFD / 128, MTOK / 128);   // N=4096 GEMM

    // 1) h = LN1(x)
    ln_kernel<<<MTOK, 256>>>(x, g1, beta1, h);
    // 2) q,k,v = h @ W{q,k,v} + b
    gemm_kernel<<<gE, blk>>>(h, Wq, bq, nullptr, q, MTOK, EMB, EMB, 0);
    gemm_kernel<<<gE, blk>>>(h, Wk, bk, nullptr, k, MTOK, EMB, EMB, 0);
    gemm_kernel<<<gE, blk>>>(h, Wv, bv, nullptr, v, MTOK, EMB, EMB, 0);
    // 3) y = causal attention(q,k,v)  -> reuse h
    attn_kernel<<<dim3(SEQ / TQ, BSZ * NH), 128>>>(q, k, v, h);
    // 4) x2 = x + y @ Wo + bo  -> d_out
    gemm_kernel<<<gE, blk>>>(h, Wo, bo, x, out, MTOK, EMB, EMB, 2);
    // 5) h2 = LN2(x2) -> reuse q
    ln_kernel<<<MTOK, 256>>>(out, g2, beta2, q);
    // 6) ff = gelu(h2 @ W1 + b1)
    gemm_kernel<<<gF, blk>>>(q, W1, b1, nullptr, ff, MTOK, FFD, EMB, 1);
    // 7) out = x2 + ff @ W2 + b2
    gemm_kernel<<<gE, blk>>>(ff, W2, b2, out, out, MTOK, EMB, FFD, 2);
}

// round 4
// speedup vs baseline: 1.6357x; 1.6357x over previous
#include <cuda_runtime.h>
#include <cuda_bf16.h>
#include <math.h>
#include <stdint.h>

#define BSZ 4
#define SEQ 2048
#define EMB 1024
#define NH 16
#define HD 64
#define FFD 4096
#define MTOK 8192   // BSZ*SEQ

// ---------------- scratch (static device arrays, allocation-free) ----------
__device__ float g_q[MTOK*EMB], g_k[MTOK*EMB], g_v[MTOK*EMB];
__device__ __nv_bfloat16 s_hh[MTOK*EMB], s_hl[MTOK*EMB];   // LN out hi/lo
__device__ __nv_bfloat16 s_yh[MTOK*EMB], s_yl[MTOK*EMB];   // attn out hi/lo
__device__ __nv_bfloat16 s_fh[MTOK*FFD], s_fl[MTOK*FFD];   // gelu out hi/lo
// transposed weights [N,K] hi/lo
__device__ __nv_bfloat16 w_qh[EMB*EMB], w_ql[EMB*EMB];
__device__ __nv_bfloat16 w_kh[EMB*EMB], w_kl[EMB*EMB];
__device__ __nv_bfloat16 w_vh[EMB*EMB], w_vl[EMB*EMB];
__device__ __nv_bfloat16 w_oh[EMB*EMB], w_ol[EMB*EMB];
__device__ __nv_bfloat16 w_1h[FFD*EMB], w_1l[FFD*EMB];
__device__ __nv_bfloat16 w_2h[EMB*FFD], w_2l[EMB*FFD];

// --------------------------- PTX helpers ------------------------------------
__device__ __forceinline__ uint32_t smem_u32(const void* p) {
    return (uint32_t)__cvta_generic_to_shared(p);
}
__device__ __forceinline__ void cp16(uint32_t dst, const void* src) {
    asm volatile("cp.async.ca.shared.global [%0], [%1], 16;" :: "r"(dst), "l"(src));
}
#define CP_COMMIT() asm volatile("cp.async.commit_group;" ::: "memory")
#define CP_WAIT1()  asm volatile("cp.async.wait_group 1;" ::: "memory")
#define CP_WAIT0()  asm volatile("cp.async.wait_group 0;" ::: "memory")

__device__ __forceinline__ void ldsm4(uint32_t* r, uint32_t addr) {
    asm volatile("ldmatrix.sync.aligned.m8n8.x4.shared.b16 {%0,%1,%2,%3}, [%4];"
        : "=r"(r[0]), "=r"(r[1]), "=r"(r[2]), "=r"(r[3]) : "r"(addr));
}
__device__ __forceinline__ void mma_bf16(float* d, const uint32_t* a, const uint32_t* b) {
    asm volatile("mma.sync.aligned.m16n8k16.row.col.f32.bf16.bf16.f32 "
        "{%0,%1,%2,%3}, {%4,%5,%6,%7}, {%8,%9}, {%0,%1,%2,%3};"
        : "+f"(d[0]), "+f"(d[1]), "+f"(d[2]), "+f"(d[3])
        : "r"(a[0]), "r"(a[1]), "r"(a[2]), "r"(a[3]), "r"(b[0]), "r"(b[1]));
}

// ---------------------- weight prepass: transpose + split -------------------
__global__ void wprep(const float* __restrict__ W, __nv_bfloat16* __restrict__ Th,
                      __nv_bfloat16* __restrict__ Tl, int K, int N)
{
    __shared__ float t[32][33];
    int n0 = blockIdx.x * 32, k0 = blockIdx.y * 32;
    int tx = threadIdx.x, ty = threadIdx.y;   // (32, 8)
    #pragma unroll
    for (int j = 0; j < 4; j++)
        t[ty + 8*j][tx] = W[(size_t)(k0 + ty + 8*j) * N + n0 + tx];
    __syncthreads();
    #pragma unroll
    for (int j = 0; j < 4; j++) {
        int n = n0 + ty + 8*j, k = k0 + tx;
        float v = t[tx][ty + 8*j];
        __nv_bfloat16 h = __float2bfloat16(v);
        Th[(size_t)n * K + k] = h;
        Tl[(size_t)n * K + k] = __float2bfloat16(v - __bfloat162float(h));
    }
}

// ---------------------------- LayerNorm (bf16 hi/lo out) --------------------
__global__ __launch_bounds__(256) void ln_kernel(
    const float* __restrict__ x, const float* __restrict__ g,
    const float* __restrict__ bta, __nv_bfloat16* __restrict__ oh,
    __nv_bfloat16* __restrict__ ol)
{
    int row = blockIdx.x;
    int t = threadIdx.x;
    const float4* xr = (const float4*)(x + (size_t)row * EMB);
    float4 v = xr[t];
    float s  = v.x + v.y + v.z + v.w;
    float ss = v.x*v.x + v.y*v.y + v.z*v.z + v.w*v.w;
    #pragma unroll
    for (int o = 16; o; o >>= 1) {
        s  += __shfl_xor_sync(0xFFFFFFFFu, s,  o);
        ss += __shfl_xor_sync(0xFFFFFFFFu, ss, o);
    }
    __shared__ float sh_s[8], sh_ss[8];
    __shared__ float s_mu, s_rstd;
    int w = t >> 5;
    if ((t & 31) == 0) { sh_s[w] = s; sh_ss[w] = ss; }
    __syncthreads();
    if (t == 0) {
        float S = 0.f, SS = 0.f;
        #pragma unroll
        for (int i = 0; i < 8; i++) { S += sh_s[i]; SS += sh_ss[i]; }
        float mu  = S * (1.0f / EMB);
        float var = SS * (1.0f / EMB) - mu * mu;
        s_mu = mu; s_rstd = rsqrtf(var + 1e-5f);
    }
    __syncthreads();
    float mu = s_mu, rs = s_rstd;
    float4 gv = ((const float4*)g)[t];
    float4 bv = ((const float4*)bta)[t];
    float o[4];
    o[0] = (v.x - mu) * rs * gv.x + bv.x;
    o[1] = (v.y - mu) * rs * gv.y + bv.y;
    o[2] = (v.z - mu) * rs * gv.z + bv.z;
    o[3] = (v.w - mu) * rs * gv.w + bv.w;
    size_t base = (size_t)row * EMB + t * 4;
    #pragma unroll
    for (int i = 0; i < 4; i++) {
        __nv_bfloat16 h = __float2bfloat16(o[i]);
        oh[base + i] = h;
        ol[base + i] = __float2bfloat16(o[i] - __bfloat162float(h));
    }
}

// ----------------------- mma.sync GEMM (bf16x3 split) ------------------------
// C[M,N] = A[M,K] @ Bt[N,K]^T; A/B pre-split hi/lo bf16, both K-major.
// mode 0: C = D+bias        mode 2: C = D+bias+resid
// mode 1: gelu(D+bias) -> (Oh, Ol) bf16 hi/lo
// CTA tile 128x128, K-chunk 32, 2-stage cp.async. 8 warps, warp tile 64x32.
#define RSTRIDE 80                // padded smem row: 32 bf16 data + 8 pad
#define MAT_BYTES (128 * RSTRIDE) // 10240
#define STAGE_BYTES (4 * MAT_BYTES)
#define SMEM_TOTAL (2 * STAGE_BYTES)

__global__ __launch_bounds__(256) void gemm_mma(
    const __nv_bfloat16* __restrict__ Ah, const __nv_bfloat16* __restrict__ Al,
    const __nv_bfloat16* __restrict__ Bh, const __nv_bfloat16* __restrict__ Bl,
    const float* __restrict__ bias, const float* __restrict__ resid,
    float* __restrict__ C, __nv_bfloat16* __restrict__ Oh,
    __nv_bfloat16* __restrict__ Ol, int M, int N, int K, int mode)
{
    extern __shared__ char smem[];
    const uint32_t sb = smem_u32(smem);
    const int tid = threadIdx.x;
    const int lane = tid & 31, warp = tid >> 5;
    const int wm = warp & 1, wn = warp >> 1;            // 2 x 4 warp grid
    const int bn = blockIdx.x * 128, bm = blockIdx.y * 128;
    const int nch = K >> 5;

    // ---- per-thread cp.async plan: 8 chunks of 16B per stage ----
    const char* gp[8];
    uint32_t sdst[8];
    #pragma unroll
    for (int i = 0; i < 8; i++) {
        int f = tid + i * 256;               // 0..2047
        int mat = f >> 9;                    // 0:Ah 1:Al 2:Bh 3:Bl
        int row = (f >> 2) & 127;
        int ch  = f & 3;
        const __nv_bfloat16* base =
            (mat == 0) ? Ah : (mat == 1) ? Al : (mat == 2) ? Bh : Bl;
        int grow = (mat < 2) ? (bm + row) : (bn + row);
        gp[i] = (const char*)(base + (size_t)grow * K + ch * 8);
        sdst[i] = sb + mat * MAT_BYTES + row * RSTRIDE + ch * 16;
    }

    float acc[4][4][4];
    #pragma unroll
    for (int i = 0; i < 4; i++)
        #pragma unroll
        for (int j = 0; j < 4; j++)
            #pragma unroll
            for (int e = 0; e < 4; e++) acc[i][j][e] = 0.f;

    // prologue: stage 0
    #pragma unroll
    for (int i = 0; i < 8; i++) { cp16(sdst[i], gp[i]); gp[i] += 64; }
    CP_COMMIT();

    const int g = lane >> 3, r = lane & 7;
    // ldmatrix lane-address components (byte offsets inside a matrix region)
    const uint32_t a_lane = (uint32_t)((wm * 64 + (g & 1) * 8 + r) * RSTRIDE + (g >> 1) * 16);
    const uint32_t b_lane = (uint32_t)((wn * 32 + (g >> 1) * 8 + r) * RSTRIDE + (g & 1) * 16);

    for (int c = 0; c < nch; c++) {
        const int s = c & 1;
        if (c + 1 < nch) {
            const uint32_t so = ((c + 1) & 1) * STAGE_BYTES;
            #pragma unroll
            for (int i = 0; i < 8; i++) { cp16(sdst[i] + so, gp[i]); gp[i] += 64; }
            CP_COMMIT();
            CP_WAIT1();
        } else {
            CP_WAIT0();
        }
        __syncthreads();

        const uint32_t st = sb + s * STAGE_BYTES;
        #pragma unroll
        for (int kk = 0; kk < 2; kk++) {
            uint32_t bh[2][4], bl[2][4];
            #pragma unroll
            for (int j = 0; j < 2; j++) {
                uint32_t baddr = st + b_lane + j * (16 * RSTRIDE) + kk * 32;
                ldsm4(bh[j], baddr + 2 * MAT_BYTES);
                ldsm4(bl[j], baddr + 3 * MAT_BYTES);
            }
            #pragma unroll
            for (int i = 0; i < 4; i++) {
                uint32_t ah[4], al[4];
                uint32_t aaddr = st + a_lane + i * (16 * RSTRIDE) + kk * 32;
                ldsm4(ah, aaddr);
                ldsm4(al, aaddr + MAT_BYTES);
                #pragma unroll
                for (int jj = 0; jj < 4; jj++) {
                    const uint32_t* Bh2 = &bh[jj >> 1][(jj & 1) * 2];
                    const uint32_t* Bl2 = &bl[jj >> 1][(jj & 1) * 2];
                    mma_bf16(acc[i][jj], ah, Bh2);
                    mma_bf16(acc[i][jj], ah, Bl2);
                    mma_bf16(acc[i][jj], al, Bh2);
                }
            }
        }
        __syncthreads();
    }

    // ---- epilogue ----
    const int rb = bm + wm * 64 + (lane >> 2);
    const int cb = bn + wn * 32 + 2 * (lane & 3);
    #pragma unroll
    for (int i = 0; i < 4; i++) {
        #pragma unroll
        for (int j = 0; j < 4; j++) {
            int row0 = rb + i * 16;
            int col  = cb + j * 8;
            float b0 = __ldg(&bias[col]), b1 = __ldg(&bias[col + 1]);
            float v00 = acc[i][j][0] + b0, v01 = acc[i][j][1] + b1;
            float v10 = acc[i][j][2] + b0, v11 = acc[i][j][3] + b1;
            if (mode == 1) {
                v00 = 0.5f * v00 * (1.0f + erff(v00 * 0.70710678118654752f));
                v01 = 0.5f * v01 * (1.0f + erff(v01 * 0.70710678118654752f));
                v10 = 0.5f * v10 * (1.0f + erff(v10 * 0.70710678118654752f));
                v11 = 0.5f * v11 * (1.0f + erff(v11 * 0.70710678118654752f));
                __nv_bfloat16 h00 = __float2bfloat16(v00);
                __nv_bfloat16 h01 = __float2bfloat16(v01);
                __nv_bfloat16 h10 = __float2bfloat16(v10);
                __nv_bfloat16 h11 = __float2bfloat16(v11);
                size_t i0 = (size_t)row0 * N + col;
                size_t i1 = (size_t)(row0 + 8) * N + col;
                *(__nv_bfloat162*)(Oh + i0) = __nv_bfloat162(h00, h01);
                *(__nv_bfloat162*)(Oh + i1) = __nv_bfloat162(h10, h11);
                *(__nv_bfloat162*)(Ol + i0) = __nv_bfloat162(
                    __float2bfloat16(v00 - __bfloat162float(h00)),
                    __float2bfloat16(v01 - __bfloat162float(h01)));
                *(__nv_bfloat162*)(Ol + i1) = __nv_bfloat162(
                    __float2bfloat16(v10 - __bfloat162float(h10)),
                    __float2bfloat16(v11 - __bfloat162float(h11)));
            } else {
                size_t i0 = (size_t)row0 * N + col;
                size_t i1 = (size_t)(row0 + 8) * N + col;
                if (mode == 2) {
                    float2 r0 = *(const float2*)(resid + i0);
                    float2 r1 = *(const float2*)(resid + i1);
                    v00 += r0.x; v01 += r0.y; v10 += r1.x; v11 += r1.y;
                }
                *(float2*)(C + i0) = make_float2(v00, v01);
                *(float2*)(C + i1) = make_float2(v10, v11);
            }
        }
    }
}

// --------------------------- Flash attention --------------------------------
#define TQ 32
#define TK 32
#define PD 65

__global__ __launch_bounds__(128) void attn_kernel(
    const float* __restrict__ Q, const float* __restrict__ Kg,
    const float* __restrict__ V, __nv_bfloat16* __restrict__ Yh,
    __nv_bfloat16* __restrict__ Yl)
{
    int qt = blockIdx.x;
    int bh = blockIdx.y;
    int b = bh >> 4, h = bh & 15;
    int tid = threadIdx.x;

    __shared__ float Qs[TQ][PD], Ks[TK][PD], Vs[TK][PD];
    __shared__ float Ss[TQ][TK + 1];
    __shared__ float m_s[TQ], l_s[TQ], corr_s[TQ];

    for (int idx = tid; idx < TQ * HD; idx += 128) {
        int r = idx >> 6, d = idx & 63;
        Qs[r][d] = Q[((size_t)(b * SEQ + qt * TQ + r)) * EMB + h * HD + d] * 0.125f;
    }
    if (tid < TQ) { m_s[tid] = -INFINITY; l_s[tid] = 0.f; }

    int r  = tid >> 2;
    int cg = tid & 3;
    float o[16];
    #pragma unroll
    for (int i = 0; i < 16; i++) o[i] = 0.f;

    for (int kt = 0; kt <= qt; kt++) {
        __syncthreads();
        for (int idx = tid; idx < TK * HD; idx += 128) {
            int rr = idx >> 6, d = idx & 63;
            size_t g = ((size_t)(b * SEQ + kt * TK + rr)) * EMB + h * HD + d;
            Ks[rr][d] = Kg[g];
            Vs[rr][d] = V[g];
        }
        __syncthreads();

        float sc[8];
        #pragma unroll
        for (int j = 0; j < 8; j++) sc[j] = 0.f;
        #pragma unroll 4
        for (int d = 0; d < HD; d++) {
            float qv = Qs[r][d];
            #pragma unroll
            for (int j = 0; j < 8; j++) sc[j] += qv * Ks[cg * 8 + j][d];
        }
        int grow = qt * TQ + r;
        #pragma unroll
        for (int j = 0; j < 8; j++) {
            int gc = kt * TK + cg * 8 + j;
            Ss[r][cg * 8 + j] = (gc <= grow) ? sc[j] : -1e30f;
        }
        __syncthreads();

        if (tid < TQ) {
            float rmax = -INFINITY;
            #pragma unroll 8
            for (int c = 0; c < TK; c++) rmax = fmaxf(rmax, Ss[tid][c]);
            float mn = fmaxf(m_s[tid], rmax);
            float corr = expf(m_s[tid] - mn);
            float sum = 0.f;
            #pragma unroll 8
            for (int c = 0; c < TK; c++) {
                float p = expf(Ss[tid][c] - mn);
                Ss[tid][c] = p;
                sum += p;
            }
            l_s[tid] = l_s[tid] * corr + sum;
            m_s[tid] = mn;
            corr_s[tid] = corr;
        }
        __syncthreads();

        float corr = corr_s[r];
        #pragma unroll
        for (int i = 0; i < 16; i++) o[i] *= corr;
        #pragma unroll 4
        for (int c = 0; c < TK; c++) {
            float p = Ss[r][c];
            #pragma unroll
            for (int i = 0; i < 16; i++) o[i] += p * Vs[c][cg * 16 + i];
        }
    }

    float inv = 1.0f / l_s[r];
    size_t base = ((size_t)(b * SEQ + qt * TQ + r)) * EMB + h * HD + cg * 16;
    #pragma unroll
    for (int i = 0; i < 16; i++) {
        float v = o[i] * inv;
        __nv_bfloat16 hh = __float2bfloat16(v);
        Yh[base + i] = hh;
        Yl[base + i] = __float2bfloat16(v - __bfloat162float(hh));
    }
}

// ------------------------------- launch -------------------------------------
extern "C" void kernel_launch(void* const* d_in, const int* in_sizes, int n_in,
                              void* d_out, int out_size)
{
    const float* x     = (const float*)d_in[0];
    const float* Wq    = (const float*)d_in[1];
    const float* bq    = (const float*)d_in[2];
    const float* Wk    = (const float*)d_in[3];
    const float* bk    = (const float*)d_in[4];
    const float* Wv    = (const float*)d_in[5];
    const float* bv    = (const float*)d_in[6];
    const float* Wo    = (const float*)d_in[7];
    const float* bo    = (const float*)d_in[8];
    const float* g1    = (const float*)d_in[9];
    const float* beta1 = (const float*)d_in[10];
    const float* g2    = (const float*)d_in[11];
    const float* beta2 = (const float*)d_in[12];
    const float* W1    = (const float*)d_in[13];
    const float* b1    = (const float*)d_in[14];
    const float* W2    = (const float*)d_in[15];
    const float* b2    = (const float*)d_in[16];
    float* out = (float*)d_out;

    float *q, *k, *v;
    __nv_bfloat16 *hh, *hl, *yh, *yl, *fh, *fl;
    __nv_bfloat16 *qh, *ql, *kh, *kl, *vh, *vl, *oh, *ol, *w1h, *w1l, *w2h, *w2l;
    cudaGetSymbolAddress((void**)&q,  g_q);
    cudaGetSymbolAddress((void**)&k,  g_k);
    cudaGetSymbolAddress((void**)&v,  g_v);
    cudaGetSymbolAddress((void**)&hh, s_hh);
    cudaGetSymbolAddress((void**)&hl, s_hl);
    cudaGetSymbolAddress((void**)&yh, s_yh);
    cudaGetSymbolAddress((void**)&yl, s_yl);
    cudaGetSymbolAddress((void**)&fh, s_fh);
    cudaGetSymbolAddress((void**)&fl, s_fl);
    cudaGetSymbolAddress((void**)&qh, w_qh);  cudaGetSymbolAddress((void**)&ql, w_ql);
    cudaGetSymbolAddress((void**)&kh, w_kh);  cudaGetSymbolAddress((void**)&kl, w_kl);
    cudaGetSymbolAddress((void**)&vh, w_vh);  cudaGetSymbolAddress((void**)&vl, w_vl);
    cudaGetSymbolAddress((void**)&oh, w_oh);  cudaGetSymbolAddress((void**)&ol, w_ol);
    cudaGetSymbolAddress((void**)&w1h, w_1h); cudaGetSymbolAddress((void**)&w1l, w_1l);
    cudaGetSymbolAddress((void**)&w2h, w_2h); cudaGetSymbolAddress((void**)&w2l, w_2l);

    cudaFuncSetAttribute(gemm_mma, cudaFuncAttributeMaxDynamicSharedMemorySize, SMEM_TOTAL);

    dim3 tb(32, 8);
    // weight prepass: transpose + bf16 hi/lo split
    wprep<<<dim3(EMB/32, EMB/32), tb>>>(Wq, qh, ql, EMB, EMB);
    wprep<<<dim3(EMB/32, EMB/32), tb>>>(Wk, kh, kl, EMB, EMB);
    wprep<<<dim3(EMB/32, EMB/32), tb>>>(Wv, vh, vl, EMB, EMB);
    wprep<<<dim3(EMB/32, EMB/32), tb>>>(Wo, oh, ol, EMB, EMB);
    wprep<<<dim3(FFD/32, EMB/32), tb>>>(W1, w1h, w1l, EMB, FFD);   // K=EMB
    wprep<<<dim3(EMB/32, FFD/32), tb>>>(W2, w2h, w2l, FFD, EMB);   // K=FFD

    dim3 gE(EMB/128, MTOK/128);
    dim3 gF(FFD/128, MTOK/128);

    // 1) h = LN1(x) -> hi/lo
    ln_kernel<<<MTOK, 256>>>(x, g1, beta1, hh, hl);
    // 2) q,k,v
    gemm_mma<<<gE, 256, SMEM_TOTAL>>>(hh, hl, qh, ql, bq, nullptr, q, nullptr, nullptr, MTOK, EMB, EMB, 0);
    gemm_mma<<<gE, 256, SMEM_TOTAL>>>(hh, hl, kh, kl, bk, nullptr, k, nullptr, nullptr, MTOK, EMB, EMB, 0);
    gemm_mma<<<gE, 256, SMEM_TOTAL>>>(hh, hl, vh, vl, bv, nullptr, v, nullptr, nullptr, MTOK, EMB, EMB, 0);
    // 3) attention -> y hi/lo
    attn_kernel<<<dim3(SEQ/TQ, BSZ*NH), 128>>>(q, k, v, yh, yl);
    // 4) x2 = x + y@Wo + bo
    gemm_mma<<<gE, 256, SMEM_TOTAL>>>(yh, yl, oh, ol, bo, x, out, nullptr, nullptr, MTOK, EMB, EMB, 2);
    // 5) h2 = LN2(x2)
    ln_kernel<<<MTOK, 256>>>(out, g2, beta2, hh, hl);
    // 6) ff = gelu(h2@W1 + b1) -> hi/lo
    gemm_mma<<<gF, 256, SMEM_TOTAL>>>(hh, hl, w1h, w1l, b1, nullptr, nullptr, fh, fl, MTOK, FFD, EMB, 1);
    // 7) out = x2 + ff@W2 + b2
    gemm_mma<<<gE, 256, SMEM_TOTAL>>>(fh, fl, w2h, w2l, b2, out, out, nullptr, nullptr, MTOK, EMB, FFD, 2);
}

// round 7
// speedup vs baseline: 3.9360x; 2.4063x over previous
#include <cuda_runtime.h>
#include <cuda_bf16.h>
#include <math.h>
#include <stdint.h>

#define BSZ 4
#define SEQ 2048
#define EMB 1024
#define NH 16
#define HD 64
#define FFD 4096
#define MTOK 8192   // BSZ*SEQ

// ---------------- scratch (static device arrays, allocation-free) ----------
__device__ __nv_bfloat16 a_qh[MTOK*EMB], a_ql[MTOK*EMB];
__device__ __nv_bfloat16 a_kh[MTOK*EMB], a_kl[MTOK*EMB];
__device__ __nv_bfloat16 a_vh[MTOK*EMB], a_vl[MTOK*EMB];
__device__ __nv_bfloat16 s_hh[MTOK*EMB], s_hl[MTOK*EMB];   // LN out hi/lo
__device__ __nv_bfloat16 s_yh[MTOK*EMB], s_yl[MTOK*EMB];   // attn out hi/lo
__device__ __nv_bfloat16 s_fh[MTOK*FFD], s_fl[MTOK*FFD];   // gelu out hi/lo
// transposed weights [N,K] hi/lo
__device__ __nv_bfloat16 w_qh[EMB*EMB], w_ql[EMB*EMB];
__device__ __nv_bfloat16 w_kh[EMB*EMB], w_kl[EMB*EMB];
__device__ __nv_bfloat16 w_vh[EMB*EMB], w_vl[EMB*EMB];
__device__ __nv_bfloat16 w_oh[EMB*EMB], w_ol[EMB*EMB];
__device__ __nv_bfloat16 w_1h[FFD*EMB], w_1l[FFD*EMB];
__device__ __nv_bfloat16 w_2h[EMB*FFD], w_2l[EMB*FFD];

// --------------------------- PTX helpers ------------------------------------
__device__ __forceinline__ uint32_t smem_u32(const void* p) {
    return (uint32_t)__cvta_generic_to_shared(p);
}
__device__ __forceinline__ void cp16(uint32_t dst, const void* src) {
    asm volatile("cp.async.ca.shared.global [%0], [%1], 16;" :: "r"(dst), "l"(src));
}
#define CP_COMMIT() asm volatile("cp.async.commit_group;" ::: "memory")
#define CP_WAIT1()  asm volatile("cp.async.wait_group 1;" ::: "memory")
#define CP_WAIT0()  asm volatile("cp.async.wait_group 0;" ::: "memory")

__device__ __forceinline__ void ldsm4(uint32_t* r, uint32_t addr) {
    asm volatile("ldmatrix.sync.aligned.m8n8.x4.shared.b16 {%0,%1,%2,%3}, [%4];"
        : "=r"(r[0]), "=r"(r[1]), "=r"(r[2]), "=r"(r[3]) : "r"(addr));
}
__device__ __forceinline__ void ldsm4t(uint32_t* r, uint32_t addr) {
    asm volatile("ldmatrix.sync.aligned.m8n8.x4.trans.shared.b16 {%0,%1,%2,%3}, [%4];"
        : "=r"(r[0]), "=r"(r[1]), "=r"(r[2]), "=r"(r[3]) : "r"(addr));
}
__device__ __forceinline__ void mma_bf16(float* d, const uint32_t* a, const uint32_t* b) {
    asm volatile("mma.sync.aligned.m16n8k16.row.col.f32.bf16.bf16.f32 "
        "{%0,%1,%2,%3}, {%4,%5,%6,%7}, {%8,%9}, {%0,%1,%2,%3};"
        : "+f"(d[0]), "+f"(d[1]), "+f"(d[2]), "+f"(d[3])
        : "r"(a[0]), "r"(a[1]), "r"(a[2]), "r"(a[3]), "r"(b[0]), "r"(b[1]));
}
// split two fp32 into packed bf16x2 hi and lo (low half = first arg)
__device__ __forceinline__ void split2(float x, float y, uint32_t& hi, uint32_t& lo) {
    __nv_bfloat16 hx = __float2bfloat16(x), hy = __float2bfloat16(y);
    __nv_bfloat162 H(hx, hy);
    __nv_bfloat162 L(__float2bfloat16(x - __bfloat162float(hx)),
                     __float2bfloat16(y - __bfloat162float(hy)));
    hi = *(uint32_t*)&H; lo = *(uint32_t*)&L;
}

// ---------------------- weight prepass: transpose + split -------------------
__global__ void wprep(const float* __restrict__ W, __nv_bfloat16* __restrict__ Th,
                      __nv_bfloat16* __restrict__ Tl, int K, int N)
{
    __shared__ float t[32][33];
    int n0 = blockIdx.x * 32, k0 = blockIdx.y * 32;
    int tx = threadIdx.x, ty = threadIdx.y;   // (32, 8)
    #pragma unroll
    for (int j = 0; j < 4; j++)
        t[ty + 8*j][tx] = W[(size_t)(k0 + ty + 8*j) * N + n0 + tx];
    __syncthreads();
    #pragma unroll
    for (int j = 0; j < 4; j++) {
        int n = n0 + ty + 8*j, k = k0 + tx;
        float v = t[tx][ty + 8*j];
        __nv_bfloat16 h = __float2bfloat16(v);
        Th[(size_t)n * K + k] = h;
        Tl[(size_t)n * K + k] = __float2bfloat16(v - __bfloat162float(h));
    }
}

// ---------------------------- LayerNorm (bf16 hi/lo out) --------------------
__global__ __launch_bounds__(256) void ln_kernel(
    const float* __restrict__ x, const float* __restrict__ g,
    const float* __restrict__ bta, __nv_bfloat16* __restrict__ oh,
    __nv_bfloat16* __restrict__ ol)
{
    int row = blockIdx.x;
    int t = threadIdx.x;
    const float4* xr = (const float4*)(x + (size_t)row * EMB);
    float4 v = xr[t];
    float s  = v.x + v.y + v.z + v.w;
    float ss = v.x*v.x + v.y*v.y + v.z*v.z + v.w*v.w;
    #pragma unroll
    for (int o = 16; o; o >>= 1) {
        s  += __shfl_xor_sync(0xFFFFFFFFu, s,  o);
        ss += __shfl_xor_sync(0xFFFFFFFFu, ss, o);
    }
    __shared__ float sh_s[8], sh_ss[8];
    __shared__ float s_mu, s_rstd;
    int w = t >> 5;
    if ((t & 31) == 0) { sh_s[w] = s; sh_ss[w] = ss; }
    __syncthreads();
    if (t == 0) {
        float S = 0.f, SS = 0.f;
        #pragma unroll
        for (int i = 0; i < 8; i++) { S += sh_s[i]; SS += sh_ss[i]; }
        float mu  = S * (1.0f / EMB);
        float var = SS * (1.0f / EMB) - mu * mu;
        s_mu = mu; s_rstd = rsqrtf(var + 1e-5f);
    }
    __syncthreads();
    float mu = s_mu, rs = s_rstd;
    float4 gv = ((const float4*)g)[t];
    float4 bv = ((const float4*)bta)[t];
    float o[4];
    o[0] = (v.x - mu) * rs * gv.x + bv.x;
    o[1] = (v.y - mu) * rs * gv.y + bv.y;
    o[2] = (v.z - mu) * rs * gv.z + bv.z;
    o[3] = (v.w - mu) * rs * gv.w + bv.w;
    size_t base = (size_t)row * EMB + t * 4;
    #pragma unroll
    for (int i = 0; i < 4; i++) {
        __nv_bfloat16 h = __float2bfloat16(o[i]);
        oh[base + i] = h;
        ol[base + i] = __float2bfloat16(o[i] - __bfloat162float(h));
    }
}

// ----------------------- mma.sync GEMM (bf16x3 split) ------------------------
// mode 0: C = D+bias   mode 2: C = D+bias+resid
// mode 1: gelu(D+bias) -> (Oh,Ol)    mode 3: D+bias -> (Oh,Ol)
#define RSTRIDE 80
#define MAT_BYTES (128 * RSTRIDE)
#define STAGE_BYTES (4 * MAT_BYTES)
#define SMEM_TOTAL (2 * STAGE_BYTES)

__global__ __launch_bounds__(256) void gemm_mma(
    const __nv_bfloat16* __restrict__ Ah, const __nv_bfloat16* __restrict__ Al,
    const __nv_bfloat16* __restrict__ Bh, const __nv_bfloat16* __restrict__ Bl,
    const float* __restrict__ bias, const float* __restrict__ resid,
    float* __restrict__ C, __nv_bfloat16* __restrict__ Oh,
    __nv_bfloat16* __restrict__ Ol, int M, int N, int K, int mode)
{
    extern __shared__ char smem[];
    const uint32_t sb = smem_u32(smem);
    const int tid = threadIdx.x;
    const int lane = tid & 31, warp = tid >> 5;
    const int wm = warp & 1, wn = warp >> 1;
    const int bn = blockIdx.x * 128, bm = blockIdx.y * 128;
    const int nch = K >> 5;

    const char* gp[8];
    uint32_t sdst[8];
    #pragma unroll
    for (int i = 0; i < 8; i++) {
        int f = tid + i * 256;
        int mat = f >> 9;
        int row = (f >> 2) & 127;
        int ch  = f & 3;
        const __nv_bfloat16* base =
            (mat == 0) ? Ah : (mat == 1) ? Al : (mat == 2) ? Bh : Bl;
        int grow = (mat < 2) ? (bm + row) : (bn + row);
        gp[i] = (const char*)(base + (size_t)grow * K + ch * 8);
        sdst[i] = sb + mat * MAT_BYTES + row * RSTRIDE + ch * 16;
    }

    float acc[4][4][4];
    #pragma unroll
    for (int i = 0; i < 4; i++)
        #pragma unroll
        for (int j = 0; j < 4; j++)
            #pragma unroll
            for (int e = 0; e < 4; e++) acc[i][j][e] = 0.f;

    #pragma unroll
    for (int i = 0; i < 8; i++) { cp16(sdst[i], gp[i]); gp[i] += 64; }
    CP_COMMIT();

    const int g = lane >> 3, r = lane & 7;
    const uint32_t a_lane = (uint32_t)((wm * 64 + (g & 1) * 8 + r) * RSTRIDE + (g >> 1) * 16);
    const uint32_t b_lane = (uint32_t)((wn * 32 + (g >> 1) * 8 + r) * RSTRIDE + (g & 1) * 16);

    for (int c = 0; c < nch; c++) {
        const int s = c & 1;
        if (c + 1 < nch) {
            const uint32_t so = ((c + 1) & 1) * STAGE_BYTES;
            #pragma unroll
            for (int i = 0; i < 8; i++) { cp16(sdst[i] + so, gp[i]); gp[i] += 64; }
            CP_COMMIT();
            CP_WAIT1();
        } else {
            CP_WAIT0();
        }
        __syncthreads();

        const uint32_t st = sb + s * STAGE_BYTES;
        #pragma unroll
        for (int kk = 0; kk < 2; kk++) {
            uint32_t bh[2][4], bl[2][4];
            #pragma unroll
            for (int j = 0; j < 2; j++) {
                uint32_t baddr = st + b_lane + j * (16 * RSTRIDE) + kk * 32;
                ldsm4(bh[j], baddr + 2 * MAT_BYTES);
                ldsm4(bl[j], baddr + 3 * MAT_BYTES);
            }
            #pragma unroll
            for (int i = 0; i < 4; i++) {
                uint32_t ah[4], al[4];
                uint32_t aaddr = st + a_lane + i * (16 * RSTRIDE) + kk * 32;
                ldsm4(ah, aaddr);
                ldsm4(al, aaddr + MAT_BYTES);
                #pragma unroll
                for (int jj = 0; jj < 4; jj++) {
                    const uint32_t* Bh2 = &bh[jj >> 1][(jj & 1) * 2];
                    const uint32_t* Bl2 = &bl[jj >> 1][(jj & 1) * 2];
                    mma_bf16(acc[i][jj], ah, Bh2);
                    mma_bf16(acc[i][jj], ah, Bl2);
                    mma_bf16(acc[i][jj], al, Bh2);
                }
            }
        }
        __syncthreads();
    }

    const int rb = bm + wm * 64 + (lane >> 2);
    const int cb = bn + wn * 32 + 2 * (lane & 3);
    #pragma unroll
    for (int i = 0; i < 4; i++) {
        #pragma unroll
        for (int j = 0; j < 4; j++) {
            int row0 = rb + i * 16;
            int col  = cb + j * 8;
            float b0 = __ldg(&bias[col]), b1 = __ldg(&bias[col + 1]);
            float v00 = acc[i][j][0] + b0, v01 = acc[i][j][1] + b1;
            float v10 = acc[i][j][2] + b0, v11 = acc[i][j][3] + b1;
            size_t i0 = (size_t)row0 * N + col;
            size_t i1 = (size_t)(row0 + 8) * N + col;
            if (mode == 1 || mode == 3) {
                if (mode == 1) {
                    v00 = 0.5f * v00 * (1.0f + erff(v00 * 0.70710678118654752f));
                    v01 = 0.5f * v01 * (1.0f + erff(v01 * 0.70710678118654752f));
                    v10 = 0.5f * v10 * (1.0f + erff(v10 * 0.70710678118654752f));
                    v11 = 0.5f * v11 * (1.0f + erff(v11 * 0.70710678118654752f));
                }
                uint32_t h0, l0, h1, l1;
                split2(v00, v01, h0, l0);
                split2(v10, v11, h1, l1);
                *(uint32_t*)(Oh + i0) = h0;
                *(uint32_t*)(Oh + i1) = h1;
                *(uint32_t*)(Ol + i0) = l0;
                *(uint32_t*)(Ol + i1) = l1;
            } else {
                if (mode == 2) {
                    float2 r0 = *(const float2*)(resid + i0);
                    float2 r1 = *(const float2*)(resid + i1);
                    v00 += r0.x; v01 += r0.y; v10 += r1.x; v11 += r1.y;
                }
                *(float2*)(C + i0) = make_float2(v00, v01);
                *(float2*)(C + i1) = make_float2(v10, v11);
            }
        }
    }
}

// ----------------- tensor-core flash attention (bf16x3 split) ---------------
#define AT_RS 144
#define AT_MAT 9216                 // 64 * 144
#define AT_QBYTES (2 * AT_MAT)      // Qh, Ql
#define AT_STAGE (4 * AT_MAT)       // Kh, Kl, Vh, Vl
#define AT_SMEM (AT_QBYTES + 2 * AT_STAGE)   // 92160

__global__ __launch_bounds__(128, 2) void attn_mma(
    const __nv_bfloat16* __restrict__ Qh_, const __nv_bfloat16* __restrict__ Ql_,
    const __nv_bfloat16* __restrict__ Kh_, const __nv_bfloat16* __restrict__ Kl_,
    const __nv_bfloat16* __restrict__ Vh_, const __nv_bfloat16* __restrict__ Vl_,
    __nv_bfloat16* __restrict__ Yh, __nv_bfloat16* __restrict__ Yl)
{
    extern __shared__ char sm[];
    const uint32_t sb = smem_u32(sm);
    const int qt = gridDim.x - 1 - blockIdx.x;          // heavy tiles first
    const int bh = blockIdx.y;
    const int b = bh >> 4, h = bh & 15;
    const int tid = threadIdx.x, lane = tid & 31, warp = tid >> 5;
    const size_t hoff = (size_t)h * HD;
    const int qtok = b * SEQ + qt * 64;

    const int r0 = tid >> 3;                    // 0..15
    const int chb = (tid & 7) * 16;             // smem byte offset
    const size_t choff = (size_t)(tid & 7) * 8; // gmem dim offset

    // ---- Q staging ----
    #pragma unroll
    for (int i = 0; i < 8; i++) {
        int mat = i >> 2, rr = i & 3;
        int row = r0 + rr * 16;
        const __nv_bfloat16* src = (mat ? Ql_ : Qh_) + (size_t)(qtok + row) * EMB + hoff + choff;
        cp16(sb + mat * AT_MAT + row * AT_RS + chb, src);
    }
    CP_COMMIT();

    // ---- K/V tile 0 ----
    int ktok = b * SEQ;
    #pragma unroll
    for (int m = 0; m < 4; m++) {
        const __nv_bfloat16* base = (m == 0) ? Kh_ : (m == 1) ? Kl_ : (m == 2) ? Vh_ : Vl_;
        #pragma unroll
        for (int rr = 0; rr < 4; rr++) {
            int row = r0 + rr * 16;
            cp16(sb + AT_QBYTES + m * AT_MAT + row * AT_RS + chb,
                 base + (size_t)(ktok + row) * EMB + hoff + choff);
        }
    }
    CP_COMMIT();
    CP_WAIT1();
    __syncthreads();

    // ---- Q fragments ----
    const int g = lane >> 3, rr8 = lane & 7;
    const uint32_t qlane = (uint32_t)((warp * 16 + (g & 1) * 8 + rr8) * AT_RS + (g >> 1) * 16);
    uint32_t qfh[4][4], qfl[4][4];
    #pragma unroll
    for (int ks = 0; ks < 4; ks++) {
        ldsm4(qfh[ks], sb + qlane + ks * 32);
        ldsm4(qfl[ks], sb + AT_MAT + qlane + ks * 32);
    }

    const uint32_t klane = (uint32_t)(((g >> 1) * 8 + rr8) * AT_RS + (g & 1) * 16);
    const int vrow = (g & 1) * 8 + rr8;
    const uint32_t vcol = (uint32_t)((g >> 1) * 16);

    float o[8][4];
    #pragma unroll
    for (int t = 0; t < 8; t++)
        #pragma unroll
        for (int e = 0; e < 4; e++) o[t][e] = 0.f;
    float m0 = -INFINITY, m1 = -INFINITY, l0 = 0.f, l1 = 0.f;
    const int rg0 = qt * 64 + warp * 16 + (lane >> 2);

    for (int c = 0; c <= qt; c++) {
        if (c < qt) {
            const uint32_t so = sb + AT_QBYTES + ((c + 1) & 1) * AT_STAGE;
            const int nt = ktok + 64;
            #pragma unroll
            for (int m = 0; m < 4; m++) {
                const __nv_bfloat16* base = (m == 0) ? Kh_ : (m == 1) ? Kl_ : (m == 2) ? Vh_ : Vl_;
                #pragma unroll
                for (int rr = 0; rr < 4; rr++) {
                    int row = r0 + rr * 16;
                    cp16(so + m * AT_MAT + row * AT_RS + chb,
                         base + (size_t)(nt + row) * EMB + hoff + choff);
                }
            }
            CP_COMMIT();
            CP_WAIT1();
        } else {
            CP_WAIT0();
        }
        __syncthreads();
        const uint32_t st = sb + AT_QBYTES + (c & 1) * AT_STAGE;

        // ---- S = Q K^T ----
        float sc[8][4];
        #pragma unroll
        for (int t = 0; t < 8; t++)
            #pragma unroll
            for (int e = 0; e < 4; e++) sc[t][e] = 0.f;
        #pragma unroll
        for (int kk = 0; kk < 4; kk++) {
            #pragma unroll
            for (int j = 0; j < 4; j++) {
                uint32_t addr = st + klane + j * (16 * AT_RS) + kk * 32;
                uint32_t kh4[4], kl4[4];
                ldsm4(kh4, addr);
                ldsm4(kl4, addr + AT_MAT);
                #pragma unroll
                for (int jj = 0; jj < 2; jj++) {
                    int t = j * 2 + jj;
                    mma_bf16(sc[t], qfh[kk], &kh4[jj * 2]);
                    mma_bf16(sc[t], qfh[kk], &kl4[jj * 2]);
                    mma_bf16(sc[t], qfl[kk], &kh4[jj * 2]);
                }
            }
        }

        // ---- scale + causal mask ----
        if (c == qt) {
            #pragma unroll
            for (int t = 0; t < 8; t++) {
                int col = c * 64 + t * 8 + (lane & 3) * 2;
                sc[t][0] = (col     <= rg0)     ? sc[t][0] * 0.125f : -1e30f;
                sc[t][1] = (col + 1 <= rg0)     ? sc[t][1] * 0.125f : -1e30f;
                sc[t][2] = (col     <= rg0 + 8) ? sc[t][2] * 0.125f : -1e30f;
                sc[t][3] = (col + 1 <= rg0 + 8) ? sc[t][3] * 0.125f : -1e30f;
            }
        } else {
            #pragma unroll
            for (int t = 0; t < 8; t++)
                #pragma unroll
                for (int e = 0; e < 4; e++) sc[t][e] *= 0.125f;
        }

        // ---- online softmax ----
        float rx0 = -INFINITY, rx1 = -INFINITY;
        #pragma unroll
        for (int t = 0; t < 8; t++) {
            rx0 = fmaxf(rx0, fmaxf(sc[t][0], sc[t][1]));
            rx1 = fmaxf(rx1, fmaxf(sc[t][2], sc[t][3]));
        }
        rx0 = fmaxf(rx0, __shfl_xor_sync(0xFFFFFFFFu, rx0, 1));
        rx0 = fmaxf(rx0, __shfl_xor_sync(0xFFFFFFFFu, rx0, 2));
        rx1 = fmaxf(rx1, __shfl_xor_sync(0xFFFFFFFFu, rx1, 1));
        rx1 = fmaxf(rx1, __shfl_xor_sync(0xFFFFFFFFu, rx1, 2));
        float mn0 = fmaxf(m0, rx0), mn1 = fmaxf(m1, rx1);
        float cr0 = __expf(m0 - mn0), cr1 = __expf(m1 - mn1);
        m0 = mn0; m1 = mn1;
        float s0 = 0.f, s1 = 0.f;
        #pragma unroll
        for (int t = 0; t < 8; t++) {
            sc[t][0] = __expf(sc[t][0] - mn0); s0 += sc[t][0];
            sc[t][1] = __expf(sc[t][1] - mn0); s0 += sc[t][1];
            sc[t][2] = __expf(sc[t][2] - mn1); s1 += sc[t][2];
            sc[t][3] = __expf(sc[t][3] - mn1); s1 += sc[t][3];
        }
        s0 += __shfl_xor_sync(0xFFFFFFFFu, s0, 1);
        s0 += __shfl_xor_sync(0xFFFFFFFFu, s0, 2);
        s1 += __shfl_xor_sync(0xFFFFFFFFu, s1, 1);
        s1 += __shfl_xor_sync(0xFFFFFFFFu, s1, 2);
        l0 = l0 * cr0 + s0;
        l1 = l1 * cr1 + s1;
        #pragma unroll
        for (int t = 0; t < 8; t++) {
            o[t][0] *= cr0; o[t][1] *= cr0; o[t][2] *= cr1; o[t][3] *= cr1;
        }

        // ---- O += P V ----
        #pragma unroll
        for (int ks = 0; ks < 4; ks++) {
            uint32_t ah[4], al[4];
            split2(sc[2*ks][0],   sc[2*ks][1],   ah[0], al[0]);
            split2(sc[2*ks][2],   sc[2*ks][3],   ah[1], al[1]);
            split2(sc[2*ks+1][0], sc[2*ks+1][1], ah[2], al[2]);
            split2(sc[2*ks+1][2], sc[2*ks+1][3], ah[3], al[3]);
            #pragma unroll
            for (int j = 0; j < 4; j++) {
                uint32_t addr = st + 2 * AT_MAT + (uint32_t)((ks * 16 + vrow) * AT_RS) + j * 32 + vcol;
                uint32_t vh4[4], vl4[4];
                ldsm4t(vh4, addr);
                ldsm4t(vl4, addr + AT_MAT);
                #pragma unroll
                for (int jj = 0; jj < 2; jj++) {
                    int t = j * 2 + jj;
                    mma_bf16(o[t], ah, &vh4[jj * 2]);
                    mma_bf16(o[t], ah, &vl4[jj * 2]);
                    mma_bf16(o[t], al, &vh4[jj * 2]);
                }
            }
        }
        __syncthreads();
        ktok += 64;
    }

    // ---- epilogue ----
    const float inv0 = 1.0f / l0, inv1 = 1.0f / l1;
    const int tok0 = b * SEQ + qt * 64 + warp * 16 + (lane >> 2);
    #pragma unroll
    for (int t = 0; t < 8; t++) {
        int col = t * 8 + (lane & 3) * 2;
        size_t i0 = (size_t)tok0 * EMB + hoff + col;
        size_t i1 = i0 + (size_t)8 * EMB;
        uint32_t h0, lo0, h1, lo1;
        split2(o[t][0] * inv0, o[t][1] * inv0, h0, lo0);
        split2(o[t][2] * inv1, o[t][3] * inv1, h1, lo1);
        *(uint32_t*)(Yh + i0) = h0;
        *(uint32_t*)(Yl + i0) = lo0;
        *(uint32_t*)(Yh + i1) = h1;
        *(uint32_t*)(Yl + i1) = lo1;
    }
}

// ------------------------------- launch -------------------------------------
extern "C" void kernel_launch(void* const* d_in, const int* in_sizes, int n_in,
                              void* d_out, int out_size)
{
    const float* x     = (const float*)d_in[0];
    const float* Wq    = (const float*)d_in[1];
    const float* bq    = (const float*)d_in[2];
    const float* Wk    = (const float*)d_in[3];
    const float* bk    = (const float*)d_in[4];
    const float* Wv    = (const float*)d_in[5];
    const float* bv    = (const float*)d_in[6];
    const float* Wo    = (const float*)d_in[7];
    const float* bo    = (const float*)d_in[8];
    const float* g1    = (const float*)d_in[9];
    const float* beta1 = (const float*)d_in[10];
    const float* g2    = (const float*)d_in[11];
    const float* beta2 = (const float*)d_in[12];
    const float* W1    = (const float*)d_in[13];
    const float* b1    = (const float*)d_in[14];
    const float* W2    = (const float*)d_in[15];
    const float* b2    = (const float*)d_in[16];
    float* out = (float*)d_out;

    __nv_bfloat16 *qh, *ql, *kh, *kl, *vh, *vl;
    __nv_bfloat16 *hh, *hl, *yh, *yl, *fh, *fl;
    __nv_bfloat16 *wqh, *wql, *wkh, *wkl, *wvh, *wvl, *woh, *wol, *w1h, *w1l, *w2h, *w2l;
    cudaGetSymbolAddress((void**)&qh, a_qh);  cudaGetSymbolAddress((void**)&ql, a_ql);
    cudaGetSymbolAddress((void**)&kh, a_kh);  cudaGetSymbolAddress((void**)&kl, a_kl);
    cudaGetSymbolAddress((void**)&vh, a_vh);  cudaGetSymbolAddress((void**)&vl, a_vl);
    cudaGetSymbolAddress((void**)&hh, s_hh);  cudaGetSymbolAddress((void**)&hl, s_hl);
    cudaGetSymbolAddress((void**)&yh, s_yh);  cudaGetSymbolAddress((void**)&yl, s_yl);
    cudaGetSymbolAddress((void**)&fh, s_fh);  cudaGetSymbolAddress((void**)&fl, s_fl);
    cudaGetSymbolAddress((void**)&wqh, w_qh); cudaGetSymbolAddress((void**)&wql, w_ql);
    cudaGetSymbolAddress((void**)&wkh, w_kh); cudaGetSymbolAddress((void**)&wkl, w_kl);
    cudaGetSymbolAddress((void**)&wvh, w_vh); cudaGetSymbolAddress((void**)&wvl, w_vl);
    cudaGetSymbolAddress((void**)&woh, w_oh); cudaGetSymbolAddress((void**)&wol, w_ol);
    cudaGetSymbolAddress((void**)&w1h, w_1h); cudaGetSymbolAddress((void**)&w1l, w_1l);
    cudaGetSymbolAddress((void**)&w2h, w_2h); cudaGetSymbolAddress((void**)&w2l, w_2l);

    cudaFuncSetAttribute(gemm_mma, cudaFuncAttributeMaxDynamicSharedMemorySize, SMEM_TOTAL);
    cudaFuncSetAttribute(attn_mma, cudaFuncAttributeMaxDynamicSharedMemorySize, AT_SMEM);

    dim3 tb(32, 8);
    wprep<<<dim3(EMB/32, EMB/32), tb>>>(Wq, wqh, wql, EMB, EMB);
    wprep<<<dim3(EMB/32, EMB/32), tb>>>(Wk, wkh, wkl, EMB, EMB);
    wprep<<<dim3(EMB/32, EMB/32), tb>>>(Wv, wvh, wvl, EMB, EMB);
    wprep<<<dim3(EMB/32, EMB/32), tb>>>(Wo, woh, wol, EMB, EMB);
    wprep<<<dim3(FFD/32, EMB/32), tb>>>(W1, w1h, w1l, EMB, FFD);
    wprep<<<dim3(EMB/32, FFD/32), tb>>>(W2, w2h, w2l, FFD, EMB);

    dim3 gE(EMB/128, MTOK/128);
    dim3 gF(FFD/128, MTOK/128);

    ln_kernel<<<MTOK, 256>>>(x, g1, beta1, hh, hl);
    gemm_mma<<<gE, 256, SMEM_TOTAL>>>(hh, hl, wqh, wql, bq, nullptr, nullptr, qh, ql, MTOK, EMB, EMB, 3);
    gemm_mma<<<gE, 256, SMEM_TOTAL>>>(hh, hl, wkh, wkl, bk, nullptr, nullptr, kh, kl, MTOK, EMB, EMB, 3);
    gemm_mma<<<gE, 256, SMEM_TOTAL>>>(hh, hl, wvh, wvl, bv, nullptr, nullptr, vh, vl, MTOK, EMB, EMB, 3);
    attn_mma<<<dim3(SEQ/64, BSZ*NH), 128, AT_SMEM>>>(qh, ql, kh, kl, vh, vl, yh, yl);
    gemm_mma<<<gE, 256, SMEM_TOTAL>>>(yh, yl, woh, wol, bo, x, out, nullptr, nullptr, MTOK, EMB, EMB, 2);
    ln_kernel<<<MTOK, 256>>>(out, g2, beta2, hh, hl);
    gemm_mma<<<gF, 256, SMEM_TOTAL>>>(hh, hl, w1h, w1l, b1, nullptr, nullptr, fh, fl, MTOK, FFD, EMB, 1);
    gemm_mma<<<gE, 256, SMEM_TOTAL>>>(fh, fl, w2h, w2l, b2, out, out, nullptr, nullptr, MTOK, EMB, FFD, 2);
}